// round 5
// baseline (speedup 1.0000x reference)
#include <cuda_runtime.h>
#include <cuda_fp16.h>

#define NR 16384
#define DIM 64
#define NT 128                    // number of 128-row strips
#define TOT (NT * (NT + 1) / 2)   // 8256 triangle tiles
// exp(sim/T) = exp2(sim * 1/(T*ln2)), T=0.5 -> scale rows by sqrt(2.885390...)
#define SQRT_SCALE 1.6986436029926783f
#define E2C 7.389056098930650f    // exp(1/T) = e^2, exact diagonal term

#define SM_TILE 9216              // 128*72 halves per buffer
// smem: B ring [3][9216]h = 55296B, then A double buffer [2][9216]h = 36864B
#define SM_A_BYTE 55296
#define SM_TOTAL_BYTE 92160

__device__ __half2 g_Y[NR * (DIM / 2)];   // normalized+scaled rows, f16
__device__ float   g_RS[NR];              // row sums of exp2(arg)
__device__ float   g_part[NR / 256];      // per-block ratio partial sums

// ---------------------------------------------------------------------------
// Kernel 1: per-row L2 normalize + scale, write f16; also zero g_RS.
// ---------------------------------------------------------------------------
__global__ void k_normalize(const float* __restrict__ x) {
    int w    = (blockIdx.x * blockDim.x + threadIdx.x) >> 5;   // row
    int lane = threadIdx.x & 31;
    float2 v = ((const float2*)x)[w * 32 + lane];
    float ss = v.x * v.x + v.y * v.y;
#pragma unroll
    for (int o = 16; o > 0; o >>= 1) ss += __shfl_xor_sync(0xffffffffu, ss, o);
    float s = SQRT_SCALE * rsqrtf(fmaxf(ss, 1e-16f));
    g_Y[w * 32 + lane] = __floats2half2_rn(v.x * s, v.y * s);
    if (lane == 0) g_RS[w] = 0.f;            // fresh accumulators each launch
}

// ---------------------------------------------------------------------------
// Kernel 2: triangular fused  exp2(Y Y^T)  ->  row sums (via row+col sums).
// 148 persistent CTAs, contiguous ranges of the 8256 (I<=J) row-major
// triangle tiles. A-strip fragments live in registers across an I-run and
// reload only on I-change. Row sums accumulate in fp32 registers per I-run
// (atomic flush on I-change); column sums reduce by shfl and go straight to
// red.global per tile. 3-stage B ring + A double buffer -> 1 sync per tile.
// ---------------------------------------------------------------------------
__device__ __forceinline__ void cp16(void* dst, const void* src) {
    unsigned d = (unsigned)__cvta_generic_to_shared(dst);
    asm volatile("cp.async.ca.shared.global [%0], [%1], 16;\n" ::"r"(d), "l"(src));
}

__device__ __forceinline__ void prefetch_tile(__half* buf, int rowbase, int tid) {
    const float4* src = (const float4*)g_Y;   // 8 halves per float4, 8 per row
#pragma unroll
    for (int it = 0; it < 4; it++) {
        int u   = tid + it * 256;             // 0..1023
        int row = u >> 3;
        int kc  = u & 7;
        cp16(buf + row * 72 + kc * 8, src + (rowbase + row) * 8 + kc);
    }
}

__device__ __forceinline__ void tri_next(int& I, int& J) {
    if (++J == NT) { I++; J = I; }
}

__global__ void __launch_bounds__(256, 1) k_main() {
    extern __shared__ __align__(16) unsigned char sm[];
    __half* bring = (__half*)sm;                 // [3][128*72]
    __half* abuf  = (__half*)(sm + SM_A_BYTE);   // [2][128*72]

    int tid  = threadIdx.x;
    int warp = tid >> 5, lane = tid & 31;
    int r = warp >> 2, c = warp & 3;
    int rbase = r * 64;
    int lr  = lane >> 2;                      // 0..7
    int lk2 = (lane & 3) * 2;                 // 0,2,4,6

    int start = (int)(((long long)TOT * blockIdx.x) / gridDim.x);
    int end   = (int)(((long long)TOT * (blockIdx.x + 1)) / gridDim.x);

    // locate starting (I, J) in row-major upper triangle
    int I = 0, acc = 0;
    while (acc + (NT - I) <= start) { acc += NT - I; I++; }
    int J = I + (start - acc);

    // ---- pipeline prologue: prefetch tiles start, start+1 ----
    prefetch_tile(abuf, I * 128, tid);                      // A slot 0
    prefetch_tile(bring + (start % 3) * SM_TILE, J * 128, tid);
    asm volatile("cp.async.commit_group;\n");

    int pI = I, pJ = J;           // prefetch cursor
    tri_next(pI, pJ);
    int lastPrefI = I, pAslot = 0;
    if (start + 1 < end) {
        if (pI != lastPrefI) { pAslot = 1; prefetch_tile(abuf + SM_TILE, pI * 128, tid); }
        prefetch_tile(bring + ((start + 1) % 3) * SM_TILE, pJ * 128, tid);
        lastPrefI = pI;
    }
    asm volatile("cp.async.commit_group;\n");
    tri_next(pI, pJ);             // cursor now at start+2

    unsigned a[4][4][4];
    float facc[8] = {0.f, 0.f, 0.f, 0.f, 0.f, 0.f, 0.f, 0.f};
    int curA = 0;
    bool loadA = true;
    int prevI = I;

    for (int p = start; p < end; p++) {
        asm volatile("cp.async.wait_group 1;\n");   // tile p (B and its A) ready
        __syncthreads();                            // also: all done with tile p-1

        // prefetch tile p+2 into ring slot (p+2)%3 (== slot of tile p-1, safe)
        if (p + 2 < end) {
            if (pI != lastPrefI) {
                pAslot ^= 1;
                prefetch_tile(abuf + pAslot * SM_TILE, pI * 128, tid);
            }
            prefetch_tile(bring + ((p + 2) % 3) * SM_TILE, pJ * 128, tid);
            lastPrefI = pI;
        }
        asm volatile("cp.async.commit_group;\n");
        tri_next(pI, pJ);

        // I-change bookkeeping: flush row accumulators, switch A buffer
        if (I != prevI) {
#pragma unroll
            for (int mf = 0; mf < 4; mf++) {
#pragma unroll
                for (int h = 0; h < 2; h++) {
                    float v = facc[mf * 2 + h];
                    v += __shfl_xor_sync(0xffffffffu, v, 1);
                    v += __shfl_xor_sync(0xffffffffu, v, 2);
                    if ((lane & 3) == 0)
                        atomicAdd(&g_RS[prevI * 128 + rbase + mf * 16 + h * 8 + lr], v);
                    facc[mf * 2 + h] = 0.f;
                }
            }
            curA ^= 1;
            loadA = true;
            prevI = I;
        }
        if (loadA) {
            const __half* smA = abuf + curA * SM_TILE;
#pragma unroll
            for (int mf = 0; mf < 4; mf++) {
#pragma unroll
                for (int kf = 0; kf < 4; kf++) {
                    const __half* ap = smA + (rbase + mf * 16 + lr) * 72 + kf * 16 + lk2;
                    a[mf][kf][0] = *(const unsigned*)(ap);
                    a[mf][kf][1] = *(const unsigned*)(ap + 8 * 72);
                    a[mf][kf][2] = *(const unsigned*)(ap + 8);
                    a[mf][kf][3] = *(const unsigned*)(ap + 8 * 72 + 8);
                }
            }
            loadA = false;
        }

        const __half* smB = bring + (p % 3) * SM_TILE;
        unsigned racc0[4] = {0, 0, 0, 0};   // f16x2 row accum (row lr)
        unsigned racc1[4] = {0, 0, 0, 0};   // (row lr+8)
        unsigned cacc[4]  = {0, 0, 0, 0};   // f16x2 col accum per s

#pragma unroll
        for (int s = 0; s < 4; s++) {
            int n0 = (c + s * 4) * 8;
            unsigned b[4][2];
            const __half* bp = smB + (n0 + lr) * 72 + lk2;
#pragma unroll
            for (int kf = 0; kf < 4; kf++) {
                b[kf][0] = *(const unsigned*)(bp + kf * 16);
                b[kf][1] = *(const unsigned*)(bp + kf * 16 + 8);
            }
#pragma unroll
            for (int mf = 0; mf < 4; mf++) {
                unsigned d0 = 0, d1 = 0;
#pragma unroll
                for (int kf = 0; kf < 4; kf++) {
                    asm("mma.sync.aligned.m16n8k16.row.col.f16.f16.f16.f16 "
                        "{%0,%1},{%2,%3,%4,%5},{%6,%7},{%0,%1};\n"
                        : "+r"(d0), "+r"(d1)
                        : "r"(a[mf][kf][0]), "r"(a[mf][kf][1]),
                          "r"(a[mf][kf][2]), "r"(a[mf][kf][3]),
                          "r"(b[kf][0]), "r"(b[kf][1]));
                }
                unsigned e0, e1;
                asm("ex2.approx.f16x2 %0, %1;" : "=r"(e0) : "r"(d0));
                asm("ex2.approx.f16x2 %0, %1;" : "=r"(e1) : "r"(d1));
                asm("add.f16x2 %0, %0, %1;" : "+r"(racc0[mf]) : "r"(e0));
                asm("add.f16x2 %0, %0, %1;" : "+r"(racc1[mf]) : "r"(e1));
                asm("add.f16x2 %0, %0, %1;" : "+r"(cacc[s]) : "r"(e0));
                asm("add.f16x2 %0, %0, %1;" : "+r"(cacc[s]) : "r"(e1));
            }
        }

        // Flush f16x2 row partials into fp32 I-run accumulators.
#pragma unroll
        for (int mf = 0; mf < 4; mf++) {
            float2 f0 = __half22float2(*reinterpret_cast<__half2*>(&racc0[mf]));
            float2 f1 = __half22float2(*reinterpret_cast<__half2*>(&racc1[mf]));
            facc[mf * 2 + 0] += f0.x + f0.y;
            facc[mf * 2 + 1] += f1.x + f1.y;
        }
        // Column sums: reduce over lr (stride-4 lanes), red.global per tile.
        if (I != J) {
#pragma unroll
            for (int s = 0; s < 4; s++) {
                float2 cf = __half22float2(*reinterpret_cast<__half2*>(&cacc[s]));
#pragma unroll
                for (int h = 0; h < 2; h++) {
                    float v = h ? cf.y : cf.x;
                    v += __shfl_xor_sync(0xffffffffu, v, 4);
                    v += __shfl_xor_sync(0xffffffffu, v, 8);
                    v += __shfl_xor_sync(0xffffffffu, v, 16);
                    if (lr == 0)
                        atomicAdd(&g_RS[J * 128 + (c + s * 4) * 8 + (lane & 3) * 2 + h], v);
                }
            }
        }
        tri_next(I, J);
    }

    // final row flush for the last I-run
#pragma unroll
    for (int mf = 0; mf < 4; mf++) {
#pragma unroll
        for (int h = 0; h < 2; h++) {
            float v = facc[mf * 2 + h];
            v += __shfl_xor_sync(0xffffffffu, v, 1);
            v += __shfl_xor_sync(0xffffffffu, v, 2);
            if ((lane & 3) == 0)
                atomicAdd(&g_RS[prevI * 128 + rbase + mf * 16 + h * 8 + lr], v);
        }
    }
}

// ---------------------------------------------------------------------------
// Kernel 3: numerator (positive pair), ratio, deterministic block partials.
// ---------------------------------------------------------------------------
__global__ void k_final() {
    __shared__ float redsm[8];
    int i = blockIdx.x * 256 + threadIdx.x;
    int j = i ^ 1;
    const __half2* yi = g_Y + i * 32;
    const __half2* yj = g_Y + j * 32;
    float dot = 0.f;
#pragma unroll
    for (int k = 0; k < 32; k++) {
        float2 av = __half22float2(yi[k]);
        float2 bv = __half22float2(yj[k]);
        dot += av.x * bv.x + av.y * bv.y;
    }
    float num   = exp2f(dot);                 // dot already carries 1/(T ln2)
    float ratio = num / (g_RS[i] - E2C);

    int lane = threadIdx.x & 31, w = threadIdx.x >> 5;
#pragma unroll
    for (int o = 16; o > 0; o >>= 1) ratio += __shfl_xor_sync(0xffffffffu, ratio, o);
    if (lane == 0) redsm[w] = ratio;
    __syncthreads();
    if (threadIdx.x < 8) {
        float v = redsm[threadIdx.x];
#pragma unroll
        for (int o = 4; o > 0; o >>= 1) v += __shfl_xor_sync(0x000000ffu, v, o);
        if (threadIdx.x == 0) g_part[blockIdx.x] = v;
    }
}

// ---------------------------------------------------------------------------
// Kernel 4: final deterministic reduce of 64 partials -> loss.
// ---------------------------------------------------------------------------
__global__ void k_loss(float* __restrict__ out) {
    __shared__ float w2[2];
    int t = threadIdx.x;            // 64 threads
    float v = g_part[t];
#pragma unroll
    for (int o = 16; o > 0; o >>= 1) v += __shfl_xor_sync(0xffffffffu, v, o);
    if ((t & 31) == 0) w2[t >> 5] = v;
    __syncthreads();
    if (t == 0) out[0] = -logf((w2[0] + w2[1]) * (1.0f / (float)NR));
}

// ---------------------------------------------------------------------------
extern "C" void kernel_launch(void* const* d_in, const int* in_sizes, int n_in,
                              void* d_out, int out_size) {
    const float* x = (const float*)d_in[0];
    cudaFuncSetAttribute(k_main, cudaFuncAttributeMaxDynamicSharedMemorySize,
                         SM_TOTAL_BYTE);
    k_normalize<<<NR / 8, 256>>>(x);     // 8 rows (warps) per block
    k_main<<<148, 256, SM_TOTAL_BYTE>>>();
    k_final<<<NR / 256, 256>>>();
    k_loss<<<1, 64>>>((float*)d_out);
}

// round 7
// speedup vs baseline: 1.1576x; 1.1576x over previous
#include <cuda_runtime.h>
#include <cuda_fp16.h>
#include <cstdint>

#define NR 16384
#define NT 128                    // 128-row strips
#define TOT (NT * (NT + 1) / 2)   // 8256 triangle tiles
// exp(sim/T) = exp2(sim * 1/(T*ln2)), T=0.5 -> scale rows by sqrt(2.885390...)
#define SQRT_SCALE 1.6986436029926783f
#define E2C 7.389056098930650f    // exp(1/T) = e^2, exact diagonal term

#define ROWB 80                   // padded smem row stride (bytes): conflict-free
#define TILE_B (128 * ROWB)       // 10240 B per tile buffer

__device__ unsigned short g_Q[NR * 32];   // e4m3 rows (64 fp8 = 32 ushort)
__device__ __half2 g_Y[NR * 32];          // f16 rows (numerator path)
__device__ float   g_RS[NR];              // row sums of exp2(arg)
__device__ float   g_part[NR / 256];      // per-block ratio partials

// ---------------------------------------------------------------------------
// Kernel 1: L2 normalize + scale; emit f16 (numerator) and e4m3 (GEMM) copies.
// ---------------------------------------------------------------------------
__global__ void k_normalize(const float* __restrict__ x) {
    int w    = (blockIdx.x * blockDim.x + threadIdx.x) >> 5;   // row
    int lane = threadIdx.x & 31;
    float2 v = ((const float2*)x)[w * 32 + lane];
    float ss = v.x * v.x + v.y * v.y;
#pragma unroll
    for (int o = 16; o > 0; o >>= 1) ss += __shfl_xor_sync(0xffffffffu, ss, o);
    float s = SQRT_SCALE * rsqrtf(fmaxf(ss, 1e-16f));
    float e0 = v.x * s, e1 = v.y * s;
    g_Y[w * 32 + lane] = __floats2half2_rn(e0, e1);
    unsigned short q;
    asm("cvt.rn.satfinite.e4m3x2.f32 %0, %1, %2;" : "=h"(q) : "f"(e1), "f"(e0));
    g_Q[w * 32 + lane] = q;
    if (lane == 0) g_RS[w] = 0.f;
}

// ---------------------------------------------------------------------------
// Kernel 2: triangular fused exp2(Q Q^T) -> row sums (rows + cols per tile).
// FP8 e4m3 m16n8k32 mma, f32 accum; 296 persistent CTAs (2/SM) over the 8256
// (I<=J) tiles. Structure identical to the best (R3) kernel otherwise.
// ---------------------------------------------------------------------------
__device__ __forceinline__ void cp16(void* dst, const void* src) {
    unsigned d = (unsigned)__cvta_generic_to_shared(dst);
    asm volatile("cp.async.ca.shared.global [%0], [%1], 16;\n" ::"r"(d), "l"(src));
}

// one 128-row x 64B fp8 tile into smem with ROWB padding
__device__ __forceinline__ void prefetch_tile(uint8_t* buf, int rowbase, int tid) {
    const char* src = (const char*)g_Q;
#pragma unroll
    for (int it = 0; it < 2; it++) {
        int u = tid + it * 256;               // 0..511 16B chunks
        int r = u >> 2, cdx = u & 3;
        cp16(buf + r * ROWB + cdx * 16,
             src + (size_t)(rowbase + r) * 64 + cdx * 16);
    }
}

__global__ void __launch_bounds__(256, 2) k_main() {
    __shared__ __align__(16) uint8_t bufA[2][TILE_B];
    __shared__ __align__(16) uint8_t bufB[2][TILE_B];
    __shared__ float red[128][4];
    __shared__ float cred[128][2];

    int tid  = threadIdx.x;
    int warp = tid >> 5, lane = tid & 31;
    int r = warp >> 2, c = warp & 3;          // row-group / column-group
    int rbase = r * 64;
    int g   = lane >> 2;                      // 0..7 (row within m16 block)
    int tig = lane & 3;                       // 0..3

    int start = (int)(((long long)TOT * blockIdx.x) / gridDim.x);
    int end   = (int)(((long long)TOT * (blockIdx.x + 1)) / gridDim.x);

    // locate starting (I, J) in row-major upper triangle
    int I = 0, acc = 0;
    while (acc + (NT - I) <= start) { acc += NT - I; I++; }
    int J = I + (start - acc);

    prefetch_tile(bufA[0], I * 128, tid);
    prefetch_tile(bufB[0], J * 128, tid);
    asm volatile("cp.async.commit_group;\n");

    for (int p = start; p < end; p++) {
        int buf = (p - start) & 1;
        int nI = I, nJ = J + 1;
        if (nJ == NT) { nI++; nJ = nI; }
        if (p + 1 < end) {
            prefetch_tile(bufA[buf ^ 1], nI * 128, tid);
            prefetch_tile(bufB[buf ^ 1], nJ * 128, tid);
            asm volatile("cp.async.commit_group;\n");
            asm volatile("cp.async.wait_group 1;\n");
        } else {
            asm volatile("cp.async.wait_group 0;\n");
        }
        __syncthreads();

        const uint8_t* smA = bufA[buf];
        const uint8_t* smB = bufB[buf];

        // A fragments: m16n8k32 e4m3. Per (mf, kc): a0:(g, k0..3) a1:(g+8)
        // a2:(g, k+16) a3:(g+8, k+16); kc selects k-base 0/32.
        unsigned a[4][2][4];
#pragma unroll
        for (int mf = 0; mf < 4; mf++) {
#pragma unroll
            for (int kc = 0; kc < 2; kc++) {
                const uint8_t* ap = smA + (rbase + mf * 16 + g) * ROWB + kc * 32 + tig * 4;
                a[mf][kc][0] = *(const unsigned*)(ap);
                a[mf][kc][1] = *(const unsigned*)(ap + 8 * ROWB);
                a[mf][kc][2] = *(const unsigned*)(ap + 16);
                a[mf][kc][3] = *(const unsigned*)(ap + 8 * ROWB + 16);
            }
        }

        unsigned racc0[4] = {0, 0, 0, 0};   // f16x2 row accum (row g)
        unsigned racc1[4] = {0, 0, 0, 0};   // (row g+8)
        unsigned cacc[4]  = {0, 0, 0, 0};   // f16x2 col accum per s

#pragma unroll
        for (int s = 0; s < 4; s++) {
            int n0 = (c + s * 4) * 8;
            unsigned b[2][2];
            const uint8_t* bp = smB + (n0 + g) * ROWB + tig * 4;
#pragma unroll
            for (int kc = 0; kc < 2; kc++) {
                b[kc][0] = *(const unsigned*)(bp + kc * 32);
                b[kc][1] = *(const unsigned*)(bp + kc * 32 + 16);
            }
#pragma unroll
            for (int mf = 0; mf < 4; mf++) {
                float d0 = 0.f, d1 = 0.f, d2 = 0.f, d3 = 0.f;
#pragma unroll
                for (int kc = 0; kc < 2; kc++) {
                    asm("mma.sync.aligned.m16n8k32.row.col.f32.e4m3.e4m3.f32 "
                        "{%0,%1,%2,%3},{%4,%5,%6,%7},{%8,%9},{%0,%1,%2,%3};\n"
                        : "+f"(d0), "+f"(d1), "+f"(d2), "+f"(d3)
                        : "r"(a[mf][kc][0]), "r"(a[mf][kc][1]),
                          "r"(a[mf][kc][2]), "r"(a[mf][kc][3]),
                          "r"(b[kc][0]), "r"(b[kc][1]));
                }
                // pack (col, col+1) -> f16x2, exp2, accumulate rows+cols
                unsigned p0, p1, e0, e1;
                asm("cvt.rn.f16x2.f32 %0, %1, %2;" : "=r"(p0) : "f"(d1), "f"(d0));
                asm("cvt.rn.f16x2.f32 %0, %1, %2;" : "=r"(p1) : "f"(d3), "f"(d2));
                asm("ex2.approx.f16x2 %0, %1;" : "=r"(e0) : "r"(p0));
                asm("ex2.approx.f16x2 %0, %1;" : "=r"(e1) : "r"(p1));
                asm("add.f16x2 %0, %0, %1;" : "+r"(racc0[mf]) : "r"(e0));
                asm("add.f16x2 %0, %0, %1;" : "+r"(racc1[mf]) : "r"(e1));
                asm("add.f16x2 %0, %0, %1;" : "+r"(cacc[s]) : "r"(e0));
                asm("add.f16x2 %0, %0, %1;" : "+r"(cacc[s]) : "r"(e1));
            }
        }

        // Row sums: lo+hi then reduce over tig (4 lanes per row).
#pragma unroll
        for (int mf = 0; mf < 4; mf++) {
            float2 f0 = __half22float2(*reinterpret_cast<__half2*>(&racc0[mf]));
            float2 f1 = __half22float2(*reinterpret_cast<__half2*>(&racc1[mf]));
            float v0 = f0.x + f0.y;
            float v1 = f1.x + f1.y;
            v0 += __shfl_xor_sync(0xffffffffu, v0, 1);
            v0 += __shfl_xor_sync(0xffffffffu, v0, 2);
            v1 += __shfl_xor_sync(0xffffffffu, v1, 1);
            v1 += __shfl_xor_sync(0xffffffffu, v1, 2);
            if (tig == 0) {
                red[rbase + mf * 16 + g][c]     = v0;
                red[rbase + mf * 16 + 8 + g][c] = v1;
            }
        }
        // Col sums: reduce over g (stride-4 lanes) per (s, half).
#pragma unroll
        for (int s = 0; s < 4; s++) {
            float2 cf = __half22float2(*reinterpret_cast<__half2*>(&cacc[s]));
#pragma unroll
            for (int h = 0; h < 2; h++) {
                float v = h ? cf.y : cf.x;
                v += __shfl_xor_sync(0xffffffffu, v, 4);
                v += __shfl_xor_sync(0xffffffffu, v, 8);
                v += __shfl_xor_sync(0xffffffffu, v, 16);
                if (g == 0)
                    cred[(c + s * 4) * 8 + tig * 2 + h][r] = v;
            }
        }
        __syncthreads();

        if (tid < 128) {
            float rs = red[tid][0] + red[tid][1] + red[tid][2] + red[tid][3];
            atomicAdd(&g_RS[I * 128 + tid], rs);
            if (I != J) {
                float cs = cred[tid][0] + cred[tid][1];
                atomicAdd(&g_RS[J * 128 + tid], cs);
            }
        }
        __syncthreads();
        I = nI; J = nJ;
    }
}

// ---------------------------------------------------------------------------
// Kernel 3: numerator (positive pair, f16 path), ratio, block partials.
// ---------------------------------------------------------------------------
__global__ void k_final() {
    __shared__ float redsm[8];
    int i = blockIdx.x * 256 + threadIdx.x;
    int j = i ^ 1;
    const __half2* yi = g_Y + i * 32;
    const __half2* yj = g_Y + j * 32;
    float dot = 0.f;
#pragma unroll
    for (int k = 0; k < 32; k++) {
        float2 av = __half22float2(yi[k]);
        float2 bv = __half22float2(yj[k]);
        dot += av.x * bv.x + av.y * bv.y;
    }
    float ratio = exp2f(dot) / (g_RS[i] - E2C);
    int lane = threadIdx.x & 31, w = threadIdx.x >> 5;
#pragma unroll
    for (int o = 16; o > 0; o >>= 1) ratio += __shfl_xor_sync(0xffffffffu, ratio, o);
    if (lane == 0) redsm[w] = ratio;
    __syncthreads();
    if (threadIdx.x < 8) {
        float v = redsm[threadIdx.x];
#pragma unroll
        for (int o = 4; o > 0; o >>= 1) v += __shfl_xor_sync(0x000000ffu, v, o);
        if (threadIdx.x == 0) g_part[blockIdx.x] = v;
    }
}

// ---------------------------------------------------------------------------
// Kernel 4: final deterministic reduce of 64 partials -> loss.
// ---------------------------------------------------------------------------
__global__ void k_loss(float* __restrict__ out) {
    __shared__ float w2[2];
    int t = threadIdx.x;            // 64 threads
    float v = g_part[t];
#pragma unroll
    for (int o = 16; o > 0; o >>= 1) v += __shfl_xor_sync(0xffffffffu, v, o);
    if ((t & 31) == 0) w2[t >> 5] = v;
    __syncthreads();
    if (t == 0) out[0] = -logf((w2[0] + w2[1]) * (1.0f / (float)NR));
}

// ---------------------------------------------------------------------------
extern "C" void kernel_launch(void* const* d_in, const int* in_sizes, int n_in,
                              void* d_out, int out_size) {
    const float* x = (const float*)d_in[0];
    k_normalize<<<NR / 8, 256>>>(x);     // 8 rows (warps) per block
    k_main<<<296, 256>>>();              // 2 CTAs per SM
    k_final<<<NR / 256, 256>>>();
    k_loss<<<1, 64>>>((float*)d_out);
}

// round 8
// speedup vs baseline: 1.3019x; 1.1246x over previous
#include <cuda_runtime.h>
#include <cuda_fp16.h>
#include <cstdint>

#define NR 16384
#define NT 128                    // 128-row strips
#define TOT (NT * (NT + 1) / 2)   // 8256 triangle tiles
// exp(sim/T) = exp2(sim * 1/(T*ln2)), T=0.5 -> scale rows by sqrt(2.885390...)
#define SQRT_SCALE 1.6986436029926783f
#define E2C 7.389056098930650f    // exp(1/T) = e^2, exact diagonal term

#define ROWB 80                   // padded smem row stride (bytes)
#define TILE_B (128 * ROWB)       // 10240 B per tile buffer

__device__ unsigned short g_Q[NR * 32];   // e4m3 rows (64 fp8 = 32 ushort)
__device__ __half2 g_Y[NR * 32];          // f16 rows (numerator path)
__device__ float   g_RS[NR];              // row sums of exp2(arg)
__device__ float   g_part[NR / 256];      // per-block ratio partials

// ---------------------------------------------------------------------------
// Kernel 1: L2 normalize + scale; emit f16 (numerator) and e4m3 (GEMM) copies.
// ---------------------------------------------------------------------------
__global__ void k_normalize(const float* __restrict__ x) {
    int w    = (blockIdx.x * blockDim.x + threadIdx.x) >> 5;   // row
    int lane = threadIdx.x & 31;
    float2 v = ((const float2*)x)[w * 32 + lane];
    float ss = v.x * v.x + v.y * v.y;
#pragma unroll
    for (int o = 16; o > 0; o >>= 1) ss += __shfl_xor_sync(0xffffffffu, ss, o);
    float s = SQRT_SCALE * rsqrtf(fmaxf(ss, 1e-16f));
    float e0 = v.x * s, e1 = v.y * s;
    g_Y[w * 32 + lane] = __floats2half2_rn(e0, e1);
    unsigned short q;
    asm("cvt.rn.satfinite.e4m3x2.f32 %0, %1, %2;" : "=h"(q) : "f"(e1), "f"(e0));
    g_Q[w * 32 + lane] = q;
    if (lane == 0) g_RS[w] = 0.f;
}

// ---------------------------------------------------------------------------
// Kernel 2: triangular fused exp2(Q Q^T) -> row sums (rows + cols per tile).
// FP8 e4m3 m16n8k32 mma with **f16 accumulators** (D already packed f16x2 ->
// ex2 directly, no cvt). 296 persistent CTAs (2/SM) over the 8256 (I<=J)
// tiles. red/cred staging double-buffered -> one __syncthreads per tile.
// ---------------------------------------------------------------------------
__device__ __forceinline__ void cp16(void* dst, const void* src) {
    unsigned d = (unsigned)__cvta_generic_to_shared(dst);
    asm volatile("cp.async.ca.shared.global [%0], [%1], 16;\n" ::"r"(d), "l"(src));
}

// one 128-row x 64B fp8 tile into smem with ROWB padding
__device__ __forceinline__ void prefetch_tile(uint8_t* buf, int rowbase, int tid) {
    const char* src = (const char*)g_Q;
#pragma unroll
    for (int it = 0; it < 2; it++) {
        int u = tid + it * 256;               // 0..511 16B chunks
        int r = u >> 2, cdx = u & 3;
        cp16(buf + r * ROWB + cdx * 16,
             src + (size_t)(rowbase + r) * 64 + cdx * 16);
    }
}

__global__ void __launch_bounds__(256, 2) k_main() {
    __shared__ __align__(16) uint8_t bufA[2][TILE_B];
    __shared__ __align__(16) uint8_t bufB[2][TILE_B];
    __shared__ float red[2][128][4];
    __shared__ float cred[2][128][2];

    int tid  = threadIdx.x;
    int warp = tid >> 5, lane = tid & 31;
    int r = warp >> 2, c = warp & 3;          // row-group / column-group
    int rbase = r * 64;
    int g   = lane >> 2;                      // 0..7 (row within m16 block)
    int tig = lane & 3;                       // 0..3

    int start = (int)(((long long)TOT * blockIdx.x) / gridDim.x);
    int end   = (int)(((long long)TOT * (blockIdx.x + 1)) / gridDim.x);

    // locate starting (I, J) in row-major upper triangle
    int I = 0, acc = 0;
    while (acc + (NT - I) <= start) { acc += NT - I; I++; }
    int J = I + (start - acc);

    prefetch_tile(bufA[0], I * 128, tid);
    prefetch_tile(bufB[0], J * 128, tid);
    asm volatile("cp.async.commit_group;\n");

    for (int p = start; p < end; p++) {
        int buf = (p - start) & 1;
        int nI = I, nJ = J + 1;
        if (nJ == NT) { nI++; nJ = nI; }
        if (p + 1 < end) {
            prefetch_tile(bufA[buf ^ 1], nI * 128, tid);
            prefetch_tile(bufB[buf ^ 1], nJ * 128, tid);
            asm volatile("cp.async.commit_group;\n");
            asm volatile("cp.async.wait_group 1;\n");
        } else {
            asm volatile("cp.async.wait_group 0;\n");
        }
        __syncthreads();    // tile p data ready; prev iter's red/cred readers done
                            // (they read buf^1 slot, which we now overwrite)

        const uint8_t* smA = bufA[buf];
        const uint8_t* smB = bufB[buf];

        // A fragments: m16n8k32 e4m3. Per (mf, kc): a0:(g,k0..3) a1:(g+8)
        // a2:(g,k+16) a3:(g+8,k+16); kc selects k-base 0/32.
        unsigned a[4][2][4];
#pragma unroll
        for (int mf = 0; mf < 4; mf++) {
#pragma unroll
            for (int kc = 0; kc < 2; kc++) {
                const uint8_t* ap = smA + (rbase + mf * 16 + g) * ROWB + kc * 32 + tig * 4;
                a[mf][kc][0] = *(const unsigned*)(ap);
                a[mf][kc][1] = *(const unsigned*)(ap + 8 * ROWB);
                a[mf][kc][2] = *(const unsigned*)(ap + 16);
                a[mf][kc][3] = *(const unsigned*)(ap + 8 * ROWB + 16);
            }
        }

        unsigned racc0[4] = {0, 0, 0, 0};   // f16x2 row accum (row g)
        unsigned racc1[4] = {0, 0, 0, 0};   // (row g+8)
        unsigned cacc[4]  = {0, 0, 0, 0};   // f16x2 col accum per s

#pragma unroll
        for (int s = 0; s < 4; s++) {
            int n0 = (c + s * 4) * 8;
            unsigned b[2][2];
            const uint8_t* bp = smB + (n0 + g) * ROWB + tig * 4;
#pragma unroll
            for (int kc = 0; kc < 2; kc++) {
                b[kc][0] = *(const unsigned*)(bp + kc * 32);
                b[kc][1] = *(const unsigned*)(bp + kc * 32 + 16);
            }
#pragma unroll
            for (int mf = 0; mf < 4; mf++) {
                unsigned d0 = 0, d1 = 0;    // f16x2 accum: {row g | g+8} cols 2tig,2tig+1
#pragma unroll
                for (int kc = 0; kc < 2; kc++) {
                    asm("mma.sync.aligned.m16n8k32.row.col.f16.e4m3.e4m3.f16 "
                        "{%0,%1},{%2,%3,%4,%5},{%6,%7},{%0,%1};\n"
                        : "+r"(d0), "+r"(d1)
                        : "r"(a[mf][kc][0]), "r"(a[mf][kc][1]),
                          "r"(a[mf][kc][2]), "r"(a[mf][kc][3]),
                          "r"(b[kc][0]), "r"(b[kc][1]));
                }
                unsigned e0, e1;
                asm("ex2.approx.f16x2 %0, %1;" : "=r"(e0) : "r"(d0));
                asm("ex2.approx.f16x2 %0, %1;" : "=r"(e1) : "r"(d1));
                asm("add.f16x2 %0, %0, %1;" : "+r"(racc0[mf]) : "r"(e0));
                asm("add.f16x2 %0, %0, %1;" : "+r"(racc1[mf]) : "r"(e1));
                asm("add.f16x2 %0, %0, %1;" : "+r"(cacc[s]) : "r"(e0));
                asm("add.f16x2 %0, %0, %1;" : "+r"(cacc[s]) : "r"(e1));
            }
        }

        // Row sums: lo+hi then reduce over tig (4 lanes per row).
#pragma unroll
        for (int mf = 0; mf < 4; mf++) {
            float2 f0 = __half22float2(*reinterpret_cast<__half2*>(&racc0[mf]));
            float2 f1 = __half22float2(*reinterpret_cast<__half2*>(&racc1[mf]));
            float v0 = f0.x + f0.y;
            float v1 = f1.x + f1.y;
            v0 += __shfl_xor_sync(0xffffffffu, v0, 1);
            v0 += __shfl_xor_sync(0xffffffffu, v0, 2);
            v1 += __shfl_xor_sync(0xffffffffu, v1, 1);
            v1 += __shfl_xor_sync(0xffffffffu, v1, 2);
            if (tig == 0) {
                red[buf][rbase + mf * 16 + g][c]     = v0;
                red[buf][rbase + mf * 16 + 8 + g][c] = v1;
            }
        }
        // Col sums: reduce over g (stride-4 lanes) per (s, half).
#pragma unroll
        for (int s = 0; s < 4; s++) {
            float2 cf = __half22float2(*reinterpret_cast<__half2*>(&cacc[s]));
#pragma unroll
            for (int h = 0; h < 2; h++) {
                float v = h ? cf.y : cf.x;
                v += __shfl_xor_sync(0xffffffffu, v, 4);
                v += __shfl_xor_sync(0xffffffffu, v, 8);
                v += __shfl_xor_sync(0xffffffffu, v, 16);
                if (g == 0)
                    cred[buf][(c + s * 4) * 8 + tig * 2 + h][r] = v;
            }
        }
        __syncthreads();    // red/cred[buf] complete; readers use it below while
                            // next iter writes the other slot

        if (tid < 128) {
            const float* rp = red[buf][tid];
            atomicAdd(&g_RS[I * 128 + tid], rp[0] + rp[1] + rp[2] + rp[3]);
            if (I != J) {
                const float* cp = cred[buf][tid];
                atomicAdd(&g_RS[J * 128 + tid], cp[0] + cp[1]);
            }
        }
        I = nI; J = nJ;
    }
}

// ---------------------------------------------------------------------------
// Kernel 3: numerator (positive pair, f16 path), ratio, block partials.
// ---------------------------------------------------------------------------
__global__ void k_final() {
    __shared__ float redsm[8];
    int i = blockIdx.x * 256 + threadIdx.x;
    int j = i ^ 1;
    const __half2* yi = g_Y + i * 32;
    const __half2* yj = g_Y + j * 32;
    float dot = 0.f;
#pragma unroll
    for (int k = 0; k < 32; k++) {
        float2 av = __half22float2(yi[k]);
        float2 bv = __half22float2(yj[k]);
        dot += av.x * bv.x + av.y * bv.y;
    }
    float ratio = exp2f(dot) / (g_RS[i] - E2C);
    int lane = threadIdx.x & 31, w = threadIdx.x >> 5;
#pragma unroll
    for (int o = 16; o > 0; o >>= 1) ratio += __shfl_xor_sync(0xffffffffu, ratio, o);
    if (lane == 0) redsm[w] = ratio;
    __syncthreads();
    if (threadIdx.x < 8) {
        float v = redsm[threadIdx.x];
#pragma unroll
        for (int o = 4; o > 0; o >>= 1) v += __shfl_xor_sync(0x000000ffu, v, o);
        if (threadIdx.x == 0) g_part[blockIdx.x] = v;
    }
}

// ---------------------------------------------------------------------------
// Kernel 4: final deterministic reduce of 64 partials -> loss.
// ---------------------------------------------------------------------------
__global__ void k_loss(float* __restrict__ out) {
    __shared__ float w2[2];
    int t = threadIdx.x;            // 64 threads
    float v = g_part[t];
#pragma unroll
    for (int o = 16; o > 0; o >>= 1) v += __shfl_xor_sync(0xffffffffu, v, o);
    if ((t & 31) == 0) w2[t >> 5] = v;
    __syncthreads();
    if (t == 0) out[0] = -logf((w2[0] + w2[1]) * (1.0f / (float)NR));
}

// ---------------------------------------------------------------------------
extern "C" void kernel_launch(void* const* d_in, const int* in_sizes, int n_in,
                              void* d_out, int out_size) {
    const float* x = (const float*)d_in[0];
    k_normalize<<<NR / 8, 256>>>(x);     // 8 rows (warps) per block
    k_main<<<296, 256>>>();              // 2 CTAs per SM
    k_final<<<NR / 256, 256>>>();
    k_loss<<<1, 64>>>((float*)d_out);
}